// round 6
// baseline (speedup 1.0000x reference)
#include <cuda_runtime.h>
#include <math.h>

// Problem constants
#define S_LEN 2048
#define E_DIM 1024
#define NH    16
#define DKH   64
#define BATCH 2
#define M_TOT (BATCH * S_LEN)   // 4096

// Scratch (static device globals: allocation-free per harness rules)
__device__ float g_Q[BATCH * NH * S_LEN * DKH];   // [B,H,S,DK]
__device__ float g_K[BATCH * NH * S_LEN * DKH];
__device__ float g_V[BATCH * NH * S_LEN * DKH];
__device__ float g_X[M_TOT * E_DIM];              // attention out, [B,S,E]

// ---------------------------------------------------------------------------
// GEMM: Y = X @ W^T + bias
//   X: [M=4096, K=1024] row-major, W: [N=1024, K=1024] row-major
//   splitHeads==1 -> scatter Y[m,n] to [B,H,S,DK]; else plain [M,N]
// Tiles: BM=BN=64, BK=16; 256 threads; 4x4 per thread.
// ---------------------------------------------------------------------------
__global__ __launch_bounds__(256) void gemm_bias_kernel(
    const float* __restrict__ X, const float* __restrict__ W,
    const float* __restrict__ bias, float* __restrict__ Y, int splitHeads)
{
    __shared__ float Xs[16][68];   // [k][m], padded
    __shared__ float Ws[16][68];   // [k][n], padded

    const int tid = threadIdx.x;
    const int tx = tid & 15;       // n-group
    const int ty = tid >> 4;       // m-group
    const int m0 = blockIdx.y * 64;
    const int n0 = blockIdx.x * 64;

    const int lr = tid >> 2;          // 0..63: row within tile
    const int lc = (tid & 3) << 2;    // 0,4,8,12: k segment
    const float* Xp = X + (size_t)(m0 + lr) * E_DIM + lc;
    const float* Wp = W + (size_t)(n0 + lr) * E_DIM + lc;

    float acc[4][4] = {};

    for (int kt = 0; kt < E_DIM; kt += 16) {
        float4 xv = *(const float4*)(Xp + kt);
        float4 wv = *(const float4*)(Wp + kt);
        __syncthreads();
        Xs[lc + 0][lr] = xv.x; Xs[lc + 1][lr] = xv.y;
        Xs[lc + 2][lr] = xv.z; Xs[lc + 3][lr] = xv.w;
        Ws[lc + 0][lr] = wv.x; Ws[lc + 1][lr] = wv.y;
        Ws[lc + 2][lr] = wv.z; Ws[lc + 3][lr] = wv.w;
        __syncthreads();

        #pragma unroll
        for (int k = 0; k < 16; k++) {
            float4 a4 = *(const float4*)&Xs[k][ty << 2];
            float4 b4 = *(const float4*)&Ws[k][tx << 2];
            float av[4] = {a4.x, a4.y, a4.z, a4.w};
            float bv[4] = {b4.x, b4.y, b4.z, b4.w};
            #pragma unroll
            for (int i = 0; i < 4; i++)
                #pragma unroll
                for (int j = 0; j < 4; j++)
                    acc[i][j] += av[i] * bv[j];
        }
    }

    float bvals[4];
    #pragma unroll
    for (int j = 0; j < 4; j++) bvals[j] = bias[n0 + (tx << 2) + j];

    #pragma unroll
    for (int i = 0; i < 4; i++) {
        const int m = m0 + (ty << 2) + i;
        #pragma unroll
        for (int j = 0; j < 4; j++) {
            const int n = n0 + (tx << 2) + j;
            const float val = acc[i][j] + bvals[j];
            if (splitHeads) {
                const int b = m >> 11, s = m & (S_LEN - 1);
                const int h = n >> 6, d = n & (DKH - 1);
                Y[((size_t)((b * NH + h) * S_LEN + s)) * DKH + d] = val;
            } else {
                Y[(size_t)m * E_DIM + n] = val;
            }
        }
    }
}

// ---------------------------------------------------------------------------
// Flash attention, fp32, causal. BQ=BKV=64, DK=64. 256 threads (16x16),
// 4x4 of the S-tile / O-tile per thread. Online softmax.
// Reads g_Q/g_K/g_V [B,H,S,DK]; writes g_X in [B,S,E] layout.
// Tile loads: 64x64 floats = 1024 float4 -> each of 256 threads loads 4.
// ---------------------------------------------------------------------------
__global__ __launch_bounds__(256) void flash_kernel()
{
    extern __shared__ float sm[];
    float (*Qs)[68] = (float(*)[68])(sm);               // [d][r]  (transposed)
    float (*Ks)[68] = (float(*)[68])(sm + 64 * 68);     // [d][c]  (transposed)
    float (*Vs)[68] = (float(*)[68])(sm + 2 * 64 * 68); // [kv][d]
    float (*Ps)[68] = (float(*)[68])(sm + 3 * 64 * 68); // [kv][r] (transposed)

    const int tid = threadIdx.x;
    const int tx = tid & 15;   // col group (kv idx for S; d idx for O)
    const int ty = tid >> 4;   // row group (q rows)
    const int qt = blockIdx.x; // q tile 0..31
    const int bh = blockIdx.y; // b*NH + h
    const int b  = bh >> 4;
    const int h  = bh & 15;

    const float* Qg = g_Q + (size_t)bh * S_LEN * DKH;
    const float* Kg = g_K + (size_t)bh * S_LEN * DKH;
    const float* Vg = g_V + (size_t)bh * S_LEN * DKH;

    const int lr  = tid >> 2;         // row 0..63
    const int lc4 = (tid & 3) << 2;   // 0,4,8,12 (base col; +16*t covers 64)

    // Load Q tile (transposed into Qs[d][r]) -- FULL 64 columns
    #pragma unroll
    for (int t = 0; t < 4; t++) {
        const int c = lc4 + 16 * t;
        float4 qv = *(const float4*)(Qg + (size_t)(qt * 64 + lr) * DKH + c);
        Qs[c + 0][lr] = qv.x; Qs[c + 1][lr] = qv.y;
        Qs[c + 2][lr] = qv.z; Qs[c + 3][lr] = qv.w;
    }

    float o[4][4] = {};
    float mprev[4], lsum[4];
    #pragma unroll
    for (int i = 0; i < 4; i++) { mprev[i] = -1e30f; lsum[i] = 0.f; }
    const float scale = 0.125f; // 1/sqrt(64)

    for (int kt = 0; kt <= qt; kt++) {
        float4 kreg[4], vreg[4];
        #pragma unroll
        for (int t = 0; t < 4; t++) {
            const int c = lc4 + 16 * t;
            kreg[t] = *(const float4*)(Kg + (size_t)(kt * 64 + lr) * DKH + c);
            vreg[t] = *(const float4*)(Vg + (size_t)(kt * 64 + lr) * DKH + c);
        }
        __syncthreads();   // prior iter's consumers of Ks/Vs done (also guards Qs store, iter 0)
        #pragma unroll
        for (int t = 0; t < 4; t++) {
            const int c = lc4 + 16 * t;
            Ks[c + 0][lr] = kreg[t].x; Ks[c + 1][lr] = kreg[t].y;
            Ks[c + 2][lr] = kreg[t].z; Ks[c + 3][lr] = kreg[t].w;
            *(float4*)&Vs[lr][c] = vreg[t];
        }
        __syncthreads();

        // S = scale * Q K^T   (this thread: rows ty*4+i, cols tx*4+j)
        float sv[4][4] = {};
        #pragma unroll 16
        for (int d = 0; d < 64; d++) {
            float4 a4 = *(const float4*)&Qs[d][ty << 2];
            float4 b4 = *(const float4*)&Ks[d][tx << 2];
            float av[4] = {a4.x, a4.y, a4.z, a4.w};
            float bv[4] = {b4.x, b4.y, b4.z, b4.w};
            #pragma unroll
            for (int i = 0; i < 4; i++)
                #pragma unroll
                for (int j = 0; j < 4; j++)
                    sv[i][j] += av[i] * bv[j];
        }

        const bool diag = (kt == qt);
        float p[4][4];
        #pragma unroll
        for (int i = 0; i < 4; i++) {
            const int r = (ty << 2) + i;
            float rm = -1e30f;
            #pragma unroll
            for (int j = 0; j < 4; j++) {
                float s = sv[i][j] * scale;
                if (diag && ((tx << 2) + j > r)) s = -1e30f;
                sv[i][j] = s;
                rm = fmaxf(rm, s);
            }
            // reduce max over 16 tx lanes (xor stays within half-warp)
            #pragma unroll
            for (int off = 8; off >= 1; off >>= 1)
                rm = fmaxf(rm, __shfl_xor_sync(0xffffffffu, rm, off));
            const float mnew = fmaxf(mprev[i], rm);
            const float alpha = __expf(mprev[i] - mnew);
            float rs = 0.f;
            #pragma unroll
            for (int j = 0; j < 4; j++) {
                const float pv = __expf(sv[i][j] - mnew);
                p[i][j] = pv;
                rs += pv;
            }
            #pragma unroll
            for (int off = 8; off >= 1; off >>= 1)
                rs += __shfl_xor_sync(0xffffffffu, rs, off);
            lsum[i] = lsum[i] * alpha + rs;
            mprev[i] = mnew;
            #pragma unroll
            for (int j = 0; j < 4; j++) o[i][j] *= alpha;
        }

        // publish P transposed: Ps[c][r]
        #pragma unroll
        for (int i = 0; i < 4; i++)
            #pragma unroll
            for (int j = 0; j < 4; j++)
                Ps[(tx << 2) + j][(ty << 2) + i] = p[i][j];
        __syncthreads();

        // O += P V   (rows ty*4+i, d-cols tx*4+j)
        #pragma unroll 16
        for (int k = 0; k < 64; k++) {
            float4 a4 = *(const float4*)&Ps[k][ty << 2];
            float4 b4 = *(const float4*)&Vs[k][tx << 2];
            float av[4] = {a4.x, a4.y, a4.z, a4.w};
            float bv[4] = {b4.x, b4.y, b4.z, b4.w};
            #pragma unroll
            for (int i = 0; i < 4; i++)
                #pragma unroll
                for (int j = 0; j < 4; j++)
                    o[i][j] += av[i] * bv[j];
        }
    }

    // Write O into [B,S,E] layout for the output projection
    #pragma unroll
    for (int i = 0; i < 4; i++) {
        const int s = qt * 64 + (ty << 2) + i;
        const float inv = 1.f / lsum[i];
        #pragma unroll
        for (int j = 0; j < 4; j++) {
            const int d = (tx << 2) + j;
            g_X[((size_t)(b * S_LEN + s)) * E_DIM + h * DKH + d] = o[i][j] * inv;
        }
    }
}

// ---------------------------------------------------------------------------
extern "C" void kernel_launch(void* const* d_in, const int* in_sizes, int n_in,
                              void* d_out, int out_size)
{
    // Input-order detection (evidence: in_sizes[0]==1024 on the bench host):
    //  (a) pytree/alphabetical: bk,bo,bq,bv, key_,mask,query,value, wk,wo,wq,wv
    //  (b) insertion order:     query,key_,value,mask, wq,bq, wk,bk, wv,bv, wo,bo
    const float *q, *k, *v, *wq, *bq, *wk, *bk, *wv, *bv, *wo, *bo;
    if (in_sizes[0] == 1024) {
        // alphabetical: bk bo bq bv key_ mask query value wk wo wq wv
        bk = (const float*)d_in[0];
        bo = (const float*)d_in[1];
        bq = (const float*)d_in[2];
        bv = (const float*)d_in[3];
        k  = (const float*)d_in[4];
        /* mask = d_in[5] (analytic causal) */
        q  = (const float*)d_in[6];
        v  = (const float*)d_in[7];
        wk = (const float*)d_in[8];
        wo = (const float*)d_in[9];
        wq = (const float*)d_in[10];
        wv = (const float*)d_in[11];
    } else {
        // insertion order: query key_ value mask wq bq wk bk wv bv wo bo
        q  = (const float*)d_in[0];
        k  = (const float*)d_in[1];
        v  = (const float*)d_in[2];
        /* mask = d_in[3] (analytic causal) */
        wq = (const float*)d_in[4];
        bq = (const float*)d_in[5];
        wk = (const float*)d_in[6];
        bk = (const float*)d_in[7];
        wv = (const float*)d_in[8];
        bv = (const float*)d_in[9];
        wo = (const float*)d_in[10];
        bo = (const float*)d_in[11];
    }

    float *pQ, *pK, *pV, *pX;
    cudaGetSymbolAddress((void**)&pQ, g_Q);
    cudaGetSymbolAddress((void**)&pK, g_K);
    cudaGetSymbolAddress((void**)&pV, g_V);
    cudaGetSymbolAddress((void**)&pX, g_X);

    const int flash_smem = 4 * 64 * 68 * (int)sizeof(float); // 69632 B
    cudaFuncSetAttribute(flash_kernel,
                         cudaFuncAttributeMaxDynamicSharedMemorySize, flash_smem);

    dim3 gg(E_DIM / 64, M_TOT / 64);  // (16, 64)
    gemm_bias_kernel<<<gg, 256>>>(q, wq, bq, pQ, 1);
    gemm_bias_kernel<<<gg, 256>>>(k, wk, bk, pK, 1);
    gemm_bias_kernel<<<gg, 256>>>(v, wv, bv, pV, 1);

    flash_kernel<<<dim3(S_LEN / 64, BATCH * NH), 256, flash_smem>>>();

    gemm_bias_kernel<<<gg, 256>>>(pX, wo, bo, (float*)d_out, 0);
}

// round 10
// speedup vs baseline: 1.5505x; 1.5505x over previous
#include <cuda_runtime.h>
#include <cuda_bf16.h>
#include <cstdint>
#include <math.h>

// Problem constants
#define S_LEN 2048
#define E_DIM 1024
#define NH    16
#define DKH   64
#define BATCH 2
#define M_TOT (BATCH * S_LEN)   // 4096

// Scratch
__device__ float g_Q[BATCH * NH * S_LEN * DKH];   // [B,H,S,DK]
__device__ float g_K[BATCH * NH * S_LEN * DKH];
__device__ float g_V[BATCH * NH * S_LEN * DKH];
__device__ float g_X[M_TOT * E_DIM];              // attention out, [B,S,E]

// ---------------------------------------------------------------------------
// Warp-level bf16 MMA (base sm_100 ISA -- NO tcgen05; harness targets sm_100).
// D(16x8,f32) += A(16x16,bf16,row) * B(16x8,bf16,col)
// ---------------------------------------------------------------------------
__device__ __forceinline__ void mma16816(float* c, const uint32_t* a, const uint32_t* b) {
    asm volatile(
        "mma.sync.aligned.m16n8k16.row.col.f32.bf16.bf16.f32 "
        "{%0,%1,%2,%3}, {%4,%5,%6,%7}, {%8,%9}, {%0,%1,%2,%3};"
        : "+f"(c[0]), "+f"(c[1]), "+f"(c[2]), "+f"(c[3])
        : "r"(a[0]), "r"(a[1]), "r"(a[2]), "r"(a[3]), "r"(b[0]), "r"(b[1]));
}

__device__ __forceinline__ void split2(float x, float y, uint32_t& hi, uint32_t& lo) {
    __nv_bfloat16 hx = __float2bfloat16_rn(x);
    __nv_bfloat16 hy = __float2bfloat16_rn(y);
    __nv_bfloat16 lx = __float2bfloat16_rn(x - __bfloat162float(hx));
    __nv_bfloat16 ly = __float2bfloat16_rn(y - __bfloat162float(hy));
    hi = (uint32_t)__bfloat16_as_ushort(hx) | ((uint32_t)__bfloat16_as_ushort(hy) << 16);
    lo = (uint32_t)__bfloat16_as_ushort(lx) | ((uint32_t)__bfloat16_as_ushort(ly) << 16);
}

// ---------------------------------------------------------------------------
// GEMM: Y = X @ W^T + bias via HMMA bf16 hi/lo 3-pass.
// X: [4096,1024] fp32; W: [1024,1024] fp32 row-major.
// BM=BN=128, BK=32; 256 threads = 8 warps; warp (wm,wn) owns 64x32.
// grid = (8, 32).
// ---------------------------------------------------------------------------
#define PITCH 20   // b32 pitch per 32-element row (conflict-free: (20g+t)%32 distinct)

__global__ __launch_bounds__(256) void gemm_mma_kernel(
    const float* __restrict__ X, const float* __restrict__ W,
    const float* __restrict__ bias, float* __restrict__ Y, int splitHeads)
{
    __shared__ uint32_t Ahi[128][PITCH];
    __shared__ uint32_t Alo[128][PITCH];
    __shared__ uint32_t Bhi[128][PITCH];
    __shared__ uint32_t Blo[128][PITCH];

    const int tid  = threadIdx.x;
    const int warp = tid >> 5;
    const int lane = tid & 31;
    const int g = lane >> 2;     // 0..7
    const int t = lane & 3;      // 0..3
    const int wm = warp >> 2;    // 0..1 : M half
    const int wn = warp & 3;     // 0..3 : N quarter
    const int m0 = blockIdx.y * 128;
    const int n0 = blockIdx.x * 128;

    float acc[4][4][4];
    #pragma unroll
    for (int i = 0; i < 4; i++)
        #pragma unroll
        for (int j = 0; j < 4; j++)
            #pragma unroll
            for (int r = 0; r < 4; r++) acc[i][j][r] = 0.f;

    for (int kc = 0; kc < E_DIM / 32; kc++) {
        const int kt = kc * 32;

        // ---- load 128x32 fp32 tiles of X and W; convert to hi/lo bf16 ----
        #pragma unroll
        for (int i = 0; i < 4; i++) {
            const int f   = tid + i * 256;   // float4 id 0..1023
            const int row = f >> 3;          // 0..127
            const int cb  = f & 7;           // float4 col 0..7
            const float4 xv = *(const float4*)(X + (size_t)(m0 + row) * E_DIM + kt + cb * 4);
            const float4 wv = *(const float4*)(W + (size_t)(n0 + row) * E_DIM + kt + cb * 4);
            uint32_t h0, l0, h1, l1;
            split2(xv.x, xv.y, h0, l0);
            split2(xv.z, xv.w, h1, l1);
            Ahi[row][cb * 2] = h0; Ahi[row][cb * 2 + 1] = h1;
            Alo[row][cb * 2] = l0; Alo[row][cb * 2 + 1] = l1;
            split2(wv.x, wv.y, h0, l0);
            split2(wv.z, wv.w, h1, l1);
            Bhi[row][cb * 2] = h0; Bhi[row][cb * 2 + 1] = h1;
            Blo[row][cb * 2] = l0; Blo[row][cb * 2 + 1] = l1;
        }
        __syncthreads();

        // ---- 2 k-steps of 16 ----
        #pragma unroll
        for (int ks = 0; ks < 2; ks++) {
            const int kb = ks * 8;   // b32 col base
            uint32_t ah[4][4], al[4][4], bh[4][2], bl[4][2];
            #pragma unroll
            for (int mi = 0; mi < 4; mi++) {
                const int r = wm * 64 + mi * 16 + g;
                ah[mi][0] = Ahi[r][kb + t];     ah[mi][1] = Ahi[r + 8][kb + t];
                ah[mi][2] = Ahi[r][kb + t + 4]; ah[mi][3] = Ahi[r + 8][kb + t + 4];
                al[mi][0] = Alo[r][kb + t];     al[mi][1] = Alo[r + 8][kb + t];
                al[mi][2] = Alo[r][kb + t + 4]; al[mi][3] = Alo[r + 8][kb + t + 4];
            }
            #pragma unroll
            for (int ni = 0; ni < 4; ni++) {
                const int r = wn * 32 + ni * 8 + g;
                bh[ni][0] = Bhi[r][kb + t]; bh[ni][1] = Bhi[r][kb + t + 4];
                bl[ni][0] = Blo[r][kb + t]; bl[ni][1] = Blo[r][kb + t + 4];
            }
            #pragma unroll
            for (int mi = 0; mi < 4; mi++)
                #pragma unroll
                for (int ni = 0; ni < 4; ni++) {
                    mma16816(acc[mi][ni], ah[mi], bh[ni]);   // hi*hi
                    mma16816(acc[mi][ni], ah[mi], bl[ni]);   // hi*lo
                    mma16816(acc[mi][ni], al[mi], bh[ni]);   // lo*hi
                }
        }
        __syncthreads();
    }

    // ---- epilogue: bias + (optional) head scatter ----
    #pragma unroll
    for (int mi = 0; mi < 4; mi++) {
        const int mlo = m0 + wm * 64 + mi * 16 + g;
        const int mhi = mlo + 8;
        #pragma unroll
        for (int ni = 0; ni < 4; ni++) {
            const int nb = n0 + wn * 32 + ni * 8 + 2 * t;
            const float bv0 = bias[nb], bv1 = bias[nb + 1];
            const float v00 = acc[mi][ni][0] + bv0;
            const float v01 = acc[mi][ni][1] + bv1;
            const float v10 = acc[mi][ni][2] + bv0;
            const float v11 = acc[mi][ni][3] + bv1;
            if (splitHeads) {
                const int b0 = mlo >> 11, s0 = mlo & (S_LEN - 1);
                const int b1 = mhi >> 11, s1 = mhi & (S_LEN - 1);
                const int h0 = nb >> 6, d0 = nb & 63;
                const int h1 = (nb + 1) >> 6, d1 = (nb + 1) & 63;
                g_Q[0]; // no-op anchor (kept trivial; compiler removes)
                Y[((size_t)((b0 * NH + h0) * S_LEN + s0)) * DKH + d0] = v00;
                Y[((size_t)((b0 * NH + h1) * S_LEN + s0)) * DKH + d1] = v01;
                Y[((size_t)((b1 * NH + h0) * S_LEN + s1)) * DKH + d0] = v10;
                Y[((size_t)((b1 * NH + h1) * S_LEN + s1)) * DKH + d1] = v11;
            } else {
                Y[(size_t)mlo * E_DIM + nb]     = v00;
                Y[(size_t)mlo * E_DIM + nb + 1] = v01;
                Y[(size_t)mhi * E_DIM + nb]     = v10;
                Y[(size_t)mhi * E_DIM + nb + 1] = v11;
            }
        }
    }
}

// ---------------------------------------------------------------------------
// Flash attention, fp32, causal (unchanged from passing round).
// ---------------------------------------------------------------------------
__global__ __launch_bounds__(256) void flash_kernel()
{
    extern __shared__ float sm[];
    float (*Qs)[68] = (float(*)[68])(sm);
    float (*Ks)[68] = (float(*)[68])(sm + 64 * 68);
    float (*Vs)[68] = (float(*)[68])(sm + 2 * 64 * 68);
    float (*Ps)[68] = (float(*)[68])(sm + 3 * 64 * 68);

    const int tid = threadIdx.x;
    const int tx = tid & 15;
    const int ty = tid >> 4;
    const int qt = blockIdx.x;
    const int bh = blockIdx.y;
    const int b  = bh >> 4;
    const int h  = bh & 15;

    const float* Qg = g_Q + (size_t)bh * S_LEN * DKH;
    const float* Kg = g_K + (size_t)bh * S_LEN * DKH;
    const float* Vg = g_V + (size_t)bh * S_LEN * DKH;

    const int lr  = tid >> 2;
    const int lc4 = (tid & 3) << 2;

    #pragma unroll
    for (int t = 0; t < 4; t++) {
        const int c = lc4 + 16 * t;
        float4 qv = *(const float4*)(Qg + (size_t)(qt * 64 + lr) * DKH + c);
        Qs[c + 0][lr] = qv.x; Qs[c + 1][lr] = qv.y;
        Qs[c + 2][lr] = qv.z; Qs[c + 3][lr] = qv.w;
    }

    float o[4][4] = {};
    float mprev[4], lsum[4];
    #pragma unroll
    for (int i = 0; i < 4; i++) { mprev[i] = -1e30f; lsum[i] = 0.f; }
    const float scale = 0.125f;

    for (int kt = 0; kt <= qt; kt++) {
        float4 kreg[4], vreg[4];
        #pragma unroll
        for (int t = 0; t < 4; t++) {
            const int c = lc4 + 16 * t;
            kreg[t] = *(const float4*)(Kg + (size_t)(kt * 64 + lr) * DKH + c);
            vreg[t] = *(const float4*)(Vg + (size_t)(kt * 64 + lr) * DKH + c);
        }
        __syncthreads();
        #pragma unroll
        for (int t = 0; t < 4; t++) {
            const int c = lc4 + 16 * t;
            Ks[c + 0][lr] = kreg[t].x; Ks[c + 1][lr] = kreg[t].y;
            Ks[c + 2][lr] = kreg[t].z; Ks[c + 3][lr] = kreg[t].w;
            *(float4*)&Vs[lr][c] = vreg[t];
        }
        __syncthreads();

        float sv[4][4] = {};
        #pragma unroll 16
        for (int d = 0; d < 64; d++) {
            float4 a4 = *(const float4*)&Qs[d][ty << 2];
            float4 b4 = *(const float4*)&Ks[d][tx << 2];
            float av[4] = {a4.x, a4.y, a4.z, a4.w};
            float bv[4] = {b4.x, b4.y, b4.z, b4.w};
            #pragma unroll
            for (int i = 0; i < 4; i++)
                #pragma unroll
                for (int j = 0; j < 4; j++)
                    sv[i][j] += av[i] * bv[j];
        }

        const bool diag = (kt == qt);
        float p[4][4];
        #pragma unroll
        for (int i = 0; i < 4; i++) {
            const int r = (ty << 2) + i;
            float rm = -1e30f;
            #pragma unroll
            for (int j = 0; j < 4; j++) {
                float s = sv[i][j] * scale;
                if (diag && ((tx << 2) + j > r)) s = -1e30f;
                sv[i][j] = s;
                rm = fmaxf(rm, s);
            }
            #pragma unroll
            for (int off = 8; off >= 1; off >>= 1)
                rm = fmaxf(rm, __shfl_xor_sync(0xffffffffu, rm, off));
            const float mnew = fmaxf(mprev[i], rm);
            const float alpha = __expf(mprev[i] - mnew);
            float rs = 0.f;
            #pragma unroll
            for (int j = 0; j < 4; j++) {
                const float pv = __expf(sv[i][j] - mnew);
                p[i][j] = pv;
                rs += pv;
            }
            #pragma unroll
            for (int off = 8; off >= 1; off >>= 1)
                rs += __shfl_xor_sync(0xffffffffu, rs, off);
            lsum[i] = lsum[i] * alpha + rs;
            mprev[i] = mnew;
            #pragma unroll
            for (int j = 0; j < 4; j++) o[i][j] *= alpha;
        }

        #pragma unroll
        for (int i = 0; i < 4; i++)
            #pragma unroll
            for (int j = 0; j < 4; j++)
                Ps[(tx << 2) + j][(ty << 2) + i] = p[i][j];
        __syncthreads();

        #pragma unroll 16
        for (int k = 0; k < 64; k++) {
            float4 a4 = *(const float4*)&Ps[k][ty << 2];
            float4 b4 = *(const float4*)&Vs[k][tx << 2];
            float av[4] = {a4.x, a4.y, a4.z, a4.w};
            float bv[4] = {b4.x, b4.y, b4.z, b4.w};
            #pragma unroll
            for (int i = 0; i < 4; i++)
                #pragma unroll
                for (int j = 0; j < 4; j++)
                    o[i][j] += av[i] * bv[j];
        }
    }

    #pragma unroll
    for (int i = 0; i < 4; i++) {
        const int s = qt * 64 + (ty << 2) + i;
        const float inv = 1.f / lsum[i];
        #pragma unroll
        for (int j = 0; j < 4; j++) {
            const int d = (tx << 2) + j;
            g_X[((size_t)(b * S_LEN + s)) * E_DIM + h * DKH + d] = o[i][j] * inv;
        }
    }
}

// ---------------------------------------------------------------------------
extern "C" void kernel_launch(void* const* d_in, const int* in_sizes, int n_in,
                              void* d_out, int out_size)
{
    const float *q, *k, *v, *wq, *bq, *wk, *bk, *wv, *bv, *wo, *bo;
    if (in_sizes[0] == 1024) {
        // alphabetical: bk bo bq bv key_ mask query value wk wo wq wv
        bk = (const float*)d_in[0];
        bo = (const float*)d_in[1];
        bq = (const float*)d_in[2];
        bv = (const float*)d_in[3];
        k  = (const float*)d_in[4];
        q  = (const float*)d_in[6];
        v  = (const float*)d_in[7];
        wk = (const float*)d_in[8];
        wo = (const float*)d_in[9];
        wq = (const float*)d_in[10];
        wv = (const float*)d_in[11];
    } else {
        // insertion order
        q  = (const float*)d_in[0];
        k  = (const float*)d_in[1];
        v  = (const float*)d_in[2];
        wq = (const float*)d_in[4];
        bq = (const float*)d_in[5];
        wk = (const float*)d_in[6];
        bk = (const float*)d_in[7];
        wv = (const float*)d_in[8];
        bv = (const float*)d_in[9];
        wo = (const float*)d_in[10];
        bo = (const float*)d_in[11];
    }

    float *pQ, *pK, *pV, *pX;
    cudaGetSymbolAddress((void**)&pQ, g_Q);
    cudaGetSymbolAddress((void**)&pK, g_K);
    cudaGetSymbolAddress((void**)&pV, g_V);
    cudaGetSymbolAddress((void**)&pX, g_X);

    const int flash_smem = 4 * 64 * 68 * (int)sizeof(float);
    cudaFuncSetAttribute(flash_kernel,
                         cudaFuncAttributeMaxDynamicSharedMemorySize, flash_smem);

    dim3 gg(E_DIM / 128, M_TOT / 128);   // (8, 32)
    gemm_mma_kernel<<<gg, 256>>>(q, wq, bq, pQ, 1);
    gemm_mma_kernel<<<gg, 256>>>(k, wk, bk, pK, 1);
    gemm_mma_kernel<<<gg, 256>>>(v, wv, bv, pV, 1);

    flash_kernel<<<dim3(S_LEN / 64, BATCH * NH), 256, flash_smem>>>();

    gemm_mma_kernel<<<gg, 256>>>(pX, wo, bo, (float*)d_out, 0);
}

// round 13
// speedup vs baseline: 2.1326x; 1.3755x over previous
#include <cuda_runtime.h>
#include <cuda_bf16.h>
#include <cstdint>
#include <math.h>

// Problem constants
#define S_LEN 2048
#define E_DIM 1024
#define NH    16
#define DKH   64
#define BATCH 2
#define M_TOT (BATCH * S_LEN)   // 4096

// Scratch
__device__ float g_Q[BATCH * NH * S_LEN * DKH];   // [B,H,S,DK]
__device__ float g_K[BATCH * NH * S_LEN * DKH];
__device__ float g_V[BATCH * NH * S_LEN * DKH];
__device__ float g_X[M_TOT * E_DIM];              // attention out, [B,S,E]

// ---------------------------------------------------------------------------
// Warp-level bf16 MMA (base sm_100 ISA).
// ---------------------------------------------------------------------------
__device__ __forceinline__ void mma16816(float* c, const uint32_t* a, const uint32_t* b) {
    asm volatile(
        "mma.sync.aligned.m16n8k16.row.col.f32.bf16.bf16.f32 "
        "{%0,%1,%2,%3}, {%4,%5,%6,%7}, {%8,%9}, {%0,%1,%2,%3};"
        : "+f"(c[0]), "+f"(c[1]), "+f"(c[2]), "+f"(c[3])
        : "r"(a[0]), "r"(a[1]), "r"(a[2]), "r"(a[3]), "r"(b[0]), "r"(b[1]));
}

__device__ __forceinline__ void split2(float x, float y, uint32_t& hi, uint32_t& lo) {
    __nv_bfloat16 hx = __float2bfloat16_rn(x);
    __nv_bfloat16 hy = __float2bfloat16_rn(y);
    __nv_bfloat16 lx = __float2bfloat16_rn(x - __bfloat162float(hx));
    __nv_bfloat16 ly = __float2bfloat16_rn(y - __bfloat162float(hy));
    hi = (uint32_t)__bfloat16_as_ushort(hx) | ((uint32_t)__bfloat16_as_ushort(hy) << 16);
    lo = (uint32_t)__bfloat16_as_ushort(lx) | ((uint32_t)__bfloat16_as_ushort(ly) << 16);
}

// ---------------------------------------------------------------------------
// GEMM: Y = X @ W^T + bias via HMMA bf16 hi/lo 3-pass (unchanged, passing).
// ---------------------------------------------------------------------------
#define PITCH 20

__global__ __launch_bounds__(256) void gemm_mma_kernel(
    const float* __restrict__ X, const float* __restrict__ W,
    const float* __restrict__ bias, float* __restrict__ Y, int splitHeads)
{
    __shared__ uint32_t Ahi[128][PITCH];
    __shared__ uint32_t Alo[128][PITCH];
    __shared__ uint32_t Bhi[128][PITCH];
    __shared__ uint32_t Blo[128][PITCH];

    const int tid  = threadIdx.x;
    const int warp = tid >> 5;
    const int lane = tid & 31;
    const int g = lane >> 2;
    const int t = lane & 3;
    const int wm = warp >> 2;
    const int wn = warp & 3;
    const int m0 = blockIdx.y * 128;
    const int n0 = blockIdx.x * 128;

    float acc[4][4][4];
    #pragma unroll
    for (int i = 0; i < 4; i++)
        #pragma unroll
        for (int j = 0; j < 4; j++)
            #pragma unroll
            for (int r = 0; r < 4; r++) acc[i][j][r] = 0.f;

    for (int kc = 0; kc < E_DIM / 32; kc++) {
        const int kt = kc * 32;
        #pragma unroll
        for (int i = 0; i < 4; i++) {
            const int f   = tid + i * 256;
            const int row = f >> 3;
            const int cb  = f & 7;
            const float4 xv = *(const float4*)(X + (size_t)(m0 + row) * E_DIM + kt + cb * 4);
            const float4 wv = *(const float4*)(W + (size_t)(n0 + row) * E_DIM + kt + cb * 4);
            uint32_t h0, l0, h1, l1;
            split2(xv.x, xv.y, h0, l0);
            split2(xv.z, xv.w, h1, l1);
            Ahi[row][cb * 2] = h0; Ahi[row][cb * 2 + 1] = h1;
            Alo[row][cb * 2] = l0; Alo[row][cb * 2 + 1] = l1;
            split2(wv.x, wv.y, h0, l0);
            split2(wv.z, wv.w, h1, l1);
            Bhi[row][cb * 2] = h0; Bhi[row][cb * 2 + 1] = h1;
            Blo[row][cb * 2] = l0; Blo[row][cb * 2 + 1] = l1;
        }
        __syncthreads();

        #pragma unroll
        for (int ks = 0; ks < 2; ks++) {
            const int kb = ks * 8;
            uint32_t ah[4][4], al[4][4], bh[4][2], bl[4][2];
            #pragma unroll
            for (int mi = 0; mi < 4; mi++) {
                const int r = wm * 64 + mi * 16 + g;
                ah[mi][0] = Ahi[r][kb + t];     ah[mi][1] = Ahi[r + 8][kb + t];
                ah[mi][2] = Ahi[r][kb + t + 4]; ah[mi][3] = Ahi[r + 8][kb + t + 4];
                al[mi][0] = Alo[r][kb + t];     al[mi][1] = Alo[r + 8][kb + t];
                al[mi][2] = Alo[r][kb + t + 4]; al[mi][3] = Alo[r + 8][kb + t + 4];
            }
            #pragma unroll
            for (int ni = 0; ni < 4; ni++) {
                const int r = wn * 32 + ni * 8 + g;
                bh[ni][0] = Bhi[r][kb + t]; bh[ni][1] = Bhi[r][kb + t + 4];
                bl[ni][0] = Blo[r][kb + t]; bl[ni][1] = Blo[r][kb + t + 4];
            }
            #pragma unroll
            for (int mi = 0; mi < 4; mi++)
                #pragma unroll
                for (int ni = 0; ni < 4; ni++) {
                    mma16816(acc[mi][ni], ah[mi], bh[ni]);
                    mma16816(acc[mi][ni], ah[mi], bl[ni]);
                    mma16816(acc[mi][ni], al[mi], bh[ni]);
                }
        }
        __syncthreads();
    }

    #pragma unroll
    for (int mi = 0; mi < 4; mi++) {
        const int mlo = m0 + wm * 64 + mi * 16 + g;
        const int mhi = mlo + 8;
        #pragma unroll
        for (int ni = 0; ni < 4; ni++) {
            const int nb = n0 + wn * 32 + ni * 8 + 2 * t;
            const float bv0 = bias[nb], bv1 = bias[nb + 1];
            const float v00 = acc[mi][ni][0] + bv0;
            const float v01 = acc[mi][ni][1] + bv1;
            const float v10 = acc[mi][ni][2] + bv0;
            const float v11 = acc[mi][ni][3] + bv1;
            if (splitHeads) {
                const int b0 = mlo >> 11, s0 = mlo & (S_LEN - 1);
                const int b1 = mhi >> 11, s1 = mhi & (S_LEN - 1);
                const int h0 = nb >> 6, d0 = nb & 63;
                const int h1 = (nb + 1) >> 6, d1 = (nb + 1) & 63;
                Y[((size_t)((b0 * NH + h0) * S_LEN + s0)) * DKH + d0] = v00;
                Y[((size_t)((b0 * NH + h1) * S_LEN + s0)) * DKH + d1] = v01;
                Y[((size_t)((b1 * NH + h0) * S_LEN + s1)) * DKH + d0] = v10;
                Y[((size_t)((b1 * NH + h1) * S_LEN + s1)) * DKH + d1] = v11;
            } else {
                Y[(size_t)mlo * E_DIM + nb]     = v00;
                Y[(size_t)mlo * E_DIM + nb + 1] = v01;
                Y[(size_t)mhi * E_DIM + nb]     = v10;
                Y[(size_t)mhi * E_DIM + nb + 1] = v11;
            }
        }
    }
}

// ---------------------------------------------------------------------------
// Flash attention via HMMA. BQ=128 (8 warps x 16 rows), BKV=64, causal.
// S accumulator sv[8][4] covers the FULL 64 kv columns (8 n-blocks of 8).
// QK^T: hi/lo 3-pass. PV: P fragments reused from S accum (FA-2 trick).
// grid = (16, 32).
// ---------------------------------------------------------------------------
#define FPITCH 36
#define FS_QHI 0
#define FS_QLO 4608
#define FS_KHI 9216
#define FS_KLO 11520
#define FS_VHI 13824
#define FS_VLO 16128
#define FS_TOTAL_B32 18432   // 73728 bytes

__global__ __launch_bounds__(256) void flash_mma_kernel()
{
    extern __shared__ uint32_t fsm[];
    uint32_t (*Qhi)[FPITCH]  = (uint32_t(*)[FPITCH])(fsm + FS_QHI);
    uint32_t (*Qlo)[FPITCH]  = (uint32_t(*)[FPITCH])(fsm + FS_QLO);
    uint32_t (*Khi)[FPITCH]  = (uint32_t(*)[FPITCH])(fsm + FS_KHI);
    uint32_t (*Klo)[FPITCH]  = (uint32_t(*)[FPITCH])(fsm + FS_KLO);
    uint32_t (*Vthi)[FPITCH] = (uint32_t(*)[FPITCH])(fsm + FS_VHI);
    uint32_t (*Vtlo)[FPITCH] = (uint32_t(*)[FPITCH])(fsm + FS_VLO);

    const int tid  = threadIdx.x;
    const int warp = tid >> 5;
    const int lane = tid & 31;
    const int g = lane >> 2;
    const int t = lane & 3;
    const int qt = (int)gridDim.x - 1 - (int)blockIdx.x;  // big tiles first
    const int bh = blockIdx.y;
    const int b  = bh >> 4;
    const int h  = bh & 15;

    const float* Qg = g_Q + (size_t)bh * S_LEN * DKH + (size_t)qt * 128 * DKH;
    const float* Kg = g_K + (size_t)bh * S_LEN * DKH;
    const float* Vg = g_V + (size_t)bh * S_LEN * DKH;

    // Load Q strip (128 x 64): 2048 float4 over 256 threads
    #pragma unroll
    for (int i = 0; i < 8; i++) {
        const int f = tid + i * 256;
        const int r = f >> 4, c4 = f & 15;
        const float4 qv = *(const float4*)(Qg + (size_t)r * DKH + c4 * 4);
        uint32_t h0, l0, h1, l1;
        split2(qv.x, qv.y, h0, l0);
        split2(qv.z, qv.w, h1, l1);
        Qhi[r][2 * c4] = h0; Qhi[r][2 * c4 + 1] = h1;
        Qlo[r][2 * c4] = l0; Qlo[r][2 * c4 + 1] = l1;
    }

    float o[8][4];
    #pragma unroll
    for (int nj = 0; nj < 8; nj++)
        #pragma unroll
        for (int r = 0; r < 4; r++) o[nj][r] = 0.f;
    float m0 = -1e30f, m1 = -1e30f, l0s = 0.f, l1s = 0.f;

    const int ntiles = 2 * qt + 2;
    for (int kt = 0; kt < ntiles; kt++) {
        const int kv0 = kt * 64;

        // K tile (64 x 64) -> Khi/Klo [kv][d-pairs]
        #pragma unroll
        for (int i = 0; i < 4; i++) {
            const int f = tid + i * 256;
            const int r = f >> 4, c4 = f & 15;
            const float4 kv4 = *(const float4*)(Kg + (size_t)(kv0 + r) * DKH + c4 * 4);
            uint32_t h0, l0, h1, l1;
            split2(kv4.x, kv4.y, h0, l0);
            split2(kv4.z, kv4.w, h1, l1);
            Khi[r][2 * c4] = h0; Khi[r][2 * c4 + 1] = h1;
            Klo[r][2 * c4] = l0; Klo[r][2 * c4 + 1] = l1;
        }
        // V tile transposed -> Vthi/Vtlo [d][kv-pairs]
        #pragma unroll
        for (int i = 0; i < 2; i++) {
            const int f = tid + i * 256;
            const int kv2 = f & 31, d4 = f >> 5;
            const float* vp = Vg + (size_t)(kv0 + 2 * kv2) * DKH + d4 * 4;
            const float4 va = *(const float4*)(vp);
            const float4 vb = *(const float4*)(vp + DKH);
            const float aa[4] = {va.x, va.y, va.z, va.w};
            const float bb[4] = {vb.x, vb.y, vb.z, vb.w};
            #pragma unroll
            for (int dd = 0; dd < 4; dd++) {
                uint32_t hh, ll;
                split2(aa[dd], bb[dd], hh, ll);
                Vthi[d4 * 4 + dd][kv2] = hh;
                Vtlo[d4 * 4 + dd][kv2] = ll;
            }
        }
        __syncthreads();

        // ---- S = Q K^T over ALL 64 kv columns (8 n-blocks), 3-pass hi/lo ----
        float sv[8][4];
        #pragma unroll
        for (int ni = 0; ni < 8; ni++)
            #pragma unroll
            for (int j = 0; j < 4; j++) sv[ni][j] = 0.f;

        const int r0 = warp * 16 + g;
        #pragma unroll
        for (int ks = 0; ks < 4; ks++) {
            const int kb = 8 * ks;
            uint32_t aqh[4], aql[4];
            aqh[0] = Qhi[r0][kb + t];     aqh[1] = Qhi[r0 + 8][kb + t];
            aqh[2] = Qhi[r0][kb + t + 4]; aqh[3] = Qhi[r0 + 8][kb + t + 4];
            aql[0] = Qlo[r0][kb + t];     aql[1] = Qlo[r0 + 8][kb + t];
            aql[2] = Qlo[r0][kb + t + 4]; aql[3] = Qlo[r0 + 8][kb + t + 4];
            #pragma unroll
            for (int ni = 0; ni < 8; ni++) {
                uint32_t bkh[2], bkl[2];
                const int kr = 8 * ni + g;
                bkh[0] = Khi[kr][kb + t]; bkh[1] = Khi[kr][kb + t + 4];
                bkl[0] = Klo[kr][kb + t]; bkl[1] = Klo[kr][kb + t + 4];
                mma16816(sv[ni], aqh, bkh);
                mma16816(sv[ni], aqh, bkl);
                mma16816(sv[ni], aql, bkh);
            }
        }

        // ---- softmax (online) ----
        const bool dm = (kt >= 2 * qt);
        const int cb = (kt - 2 * qt) * 64;
        float mx0 = -1e30f, mx1 = -1e30f;
        #pragma unroll
        for (int ni = 0; ni < 8; ni++) {
            #pragma unroll
            for (int j = 0; j < 4; j++) {
                float s = sv[ni][j] * 0.125f;
                if (dm) {
                    const int c = cb + 8 * ni + 2 * t + (j & 1);
                    const int r = (j < 2) ? r0 : (r0 + 8);
                    if (c > r) s = -1e30f;
                }
                sv[ni][j] = s;
            }
            mx0 = fmaxf(mx0, fmaxf(sv[ni][0], sv[ni][1]));
            mx1 = fmaxf(mx1, fmaxf(sv[ni][2], sv[ni][3]));
        }
        mx0 = fmaxf(mx0, __shfl_xor_sync(0xffffffffu, mx0, 1));
        mx0 = fmaxf(mx0, __shfl_xor_sync(0xffffffffu, mx0, 2));
        mx1 = fmaxf(mx1, __shfl_xor_sync(0xffffffffu, mx1, 1));
        mx1 = fmaxf(mx1, __shfl_xor_sync(0xffffffffu, mx1, 2));

        const float m0n = fmaxf(m0, mx0);
        const float m1n = fmaxf(m1, mx1);
        const float a0 = __expf(m0 - m0n);
        const float a1 = __expf(m1 - m1n);
        float rs0 = 0.f, rs1 = 0.f;
        #pragma unroll
        for (int ni = 0; ni < 8; ni++) {
            sv[ni][0] = __expf(sv[ni][0] - m0n);
            sv[ni][1] = __expf(sv[ni][1] - m0n);
            sv[ni][2] = __expf(sv[ni][2] - m1n);
            sv[ni][3] = __expf(sv[ni][3] - m1n);
            rs0 += sv[ni][0] + sv[ni][1];
            rs1 += sv[ni][2] + sv[ni][3];
        }
        rs0 += __shfl_xor_sync(0xffffffffu, rs0, 1);
        rs0 += __shfl_xor_sync(0xffffffffu, rs0, 2);
        rs1 += __shfl_xor_sync(0xffffffffu, rs1, 1);
        rs1 += __shfl_xor_sync(0xffffffffu, rs1, 2);
        l0s = l0s * a0 + rs0;
        l1s = l1s * a1 + rs1;
        m0 = m0n; m1 = m1n;
        #pragma unroll
        for (int nj = 0; nj < 8; nj++) {
            o[nj][0] *= a0; o[nj][1] *= a0;
            o[nj][2] *= a1; o[nj][3] *= a1;
        }

        // ---- P fragments straight from S accumulators (hi/lo) ----
        uint32_t aph[4][4], apl[4][4];
        #pragma unroll
        for (int ks = 0; ks < 4; ks++) {
            split2(sv[2*ks][0],   sv[2*ks][1],   aph[ks][0], apl[ks][0]);
            split2(sv[2*ks][2],   sv[2*ks][3],   aph[ks][1], apl[ks][1]);
            split2(sv[2*ks+1][0], sv[2*ks+1][1], aph[ks][2], apl[ks][2]);
            split2(sv[2*ks+1][2], sv[2*ks+1][3], aph[ks][3], apl[ks][3]);
        }

        // ---- O += P V (3-pass) ----
        #pragma unroll
        for (int nj = 0; nj < 8; nj++) {
            const int vr = 8 * nj + g;
            #pragma unroll
            for (int ks = 0; ks < 4; ks++) {
                const int kb = 8 * ks;
                uint32_t bvh[2], bvl[2];
                bvh[0] = Vthi[vr][kb + t]; bvh[1] = Vthi[vr][kb + t + 4];
                bvl[0] = Vtlo[vr][kb + t]; bvl[1] = Vtlo[vr][kb + t + 4];
                mma16816(o[nj], aph[ks], bvh);
                mma16816(o[nj], aph[ks], bvl);
                mma16816(o[nj], apl[ks], bvh);
            }
        }
        __syncthreads();
    }

    // ---- epilogue: O / l -> g_X [B,S,E] ----
    const float i0 = 1.f / l0s;
    const float i1 = 1.f / l1s;
    const int s0 = qt * 128 + warp * 16 + g;
    float* X0 = g_X + ((size_t)(b * S_LEN + s0)) * E_DIM + h * DKH;
    float* X1 = X0 + 8 * E_DIM;
    #pragma unroll
    for (int nj = 0; nj < 8; nj++) {
        const int d = 8 * nj + 2 * t;
        *(float2*)(X0 + d) = make_float2(o[nj][0] * i0, o[nj][1] * i0);
        *(float2*)(X1 + d) = make_float2(o[nj][2] * i1, o[nj][3] * i1);
    }
}

// ---------------------------------------------------------------------------
extern "C" void kernel_launch(void* const* d_in, const int* in_sizes, int n_in,
                              void* d_out, int out_size)
{
    const float *q, *k, *v, *wq, *bq, *wk, *bk, *wv, *bv, *wo, *bo;
    if (in_sizes[0] == 1024) {
        // alphabetical: bk bo bq bv key_ mask query value wk wo wq wv
        bk = (const float*)d_in[0];
        bo = (const float*)d_in[1];
        bq = (const float*)d_in[2];
        bv = (const float*)d_in[3];
        k  = (const float*)d_in[4];
        q  = (const float*)d_in[6];
        v  = (const float*)d_in[7];
        wk = (const float*)d_in[8];
        wo = (const float*)d_in[9];
        wq = (const float*)d_in[10];
        wv = (const float*)d_in[11];
    } else {
        // insertion order
        q  = (const float*)d_in[0];
        k  = (const float*)d_in[1];
        v  = (const float*)d_in[2];
        wq = (const float*)d_in[4];
        bq = (const float*)d_in[5];
        wk = (const float*)d_in[6];
        bk = (const float*)d_in[7];
        wv = (const float*)d_in[8];
        bv = (const float*)d_in[9];
        wo = (const float*)d_in[10];
        bo = (const float*)d_in[11];
    }

    float *pQ, *pK, *pV, *pX;
    cudaGetSymbolAddress((void**)&pQ, g_Q);
    cudaGetSymbolAddress((void**)&pK, g_K);
    cudaGetSymbolAddress((void**)&pV, g_V);
    cudaGetSymbolAddress((void**)&pX, g_X);

    const int flash_smem = FS_TOTAL_B32 * (int)sizeof(uint32_t); // 73728
    cudaFuncSetAttribute(flash_mma_kernel,
                         cudaFuncAttributeMaxDynamicSharedMemorySize, flash_smem);

    dim3 gg(E_DIM / 128, M_TOT / 128);   // (8, 32)
    gemm_mma_kernel<<<gg, 256>>>(q, wq, bq, pQ, 1);
    gemm_mma_kernel<<<gg, 256>>>(k, wk, bk, pK, 1);
    gemm_mma_kernel<<<gg, 256>>>(v, wv, bv, pV, 1);

    flash_mma_kernel<<<dim3(S_LEN / 128, BATCH * NH), 256, flash_smem>>>();

    gemm_mma_kernel<<<gg, 256>>>(pX, wo, bo, (float*)d_out, 0);
}